// round 1
// baseline (speedup 1.0000x reference)
#include <cuda_runtime.h>
#include <math.h>

// ---------------------------------------------------------------------------
// Problem constants
//   x: (16384, 3, 400)  -> output (16384, 140)
//   Attention collapses (seq=1, softmax over singleton) to xe @ Weff + beff.
//   GRU h0=0 -> recurrent matmuls vanish; only flat @ K GEMMs remain.
// ---------------------------------------------------------------------------
#define NROWS   16384
#define DMODEL  400
#define PDIM    6400      // H*KD = 16*400
#define FLATK   1600
#define G3      5400      // 3*GU
#define GUC     1800
#define X1C     3600
#define CATC    7200
#define OUTC    140

// Scratch (device globals; allocation at module load, allowed by harness rules)
__device__ float g_Weff[DMODEL * DMODEL];
__device__ float g_beff[DMODEL];
__device__ float g_flat[(size_t)NROWS * FLATK];
__device__ float g_G   [(size_t)NROWS * G3];
__device__ float g_x1  [(size_t)NROWS * X1C];
__device__ float g_x3  [(size_t)NROWS * GUC];
__device__ float g_x5  [(size_t)NROWS * GUC];

__device__ __forceinline__ float eluf(float v)     { return v > 0.f ? v : expm1f(v); }
__device__ __forceinline__ float sigmoidf_(float v){ return 1.f / (1.f + expf(-v)); }

// ---------------------------------------------------------------------------
// Generic tiled SGEMM:  C = [C +] A(MxK) @ B(KxN) [+ bias] [, elu]
// BM=BN=128, BK=8, 256 threads, 8x8 per-thread microtile.
// ---------------------------------------------------------------------------
#define BM 128
#define BN 128
#define BK 8

__global__ __launch_bounds__(256)
void gemm_kernel(const float* __restrict__ A, const float* __restrict__ B,
                 const float* __restrict__ bias, float* __restrict__ C,
                 int M, int N, int K, int act, int accum)
{
    __shared__ float As[BK][BM];
    __shared__ float Bs[BK][BN];

    const int tid = threadIdx.x;
    const int tx  = tid % 16;        // N direction
    const int ty  = tid / 16;        // M direction
    const int row0 = blockIdx.y * BM;
    const int col0 = blockIdx.x * BN;

    float acc[8][8];
    #pragma unroll
    for (int i = 0; i < 8; i++)
        #pragma unroll
        for (int j = 0; j < 8; j++) acc[i][j] = 0.f;

    for (int k0 = 0; k0 < K; k0 += BK) {
        // Load A tile (BM x BK)
        #pragma unroll
        for (int i = tid; i < BM * BK; i += 256) {
            int r = i / BK, c = i % BK;
            int gr = row0 + r, gc = k0 + c;
            As[c][r] = (gr < M) ? A[(size_t)gr * K + gc] : 0.f;
        }
        // Load B tile (BK x BN)
        #pragma unroll
        for (int i = tid; i < BK * BN; i += 256) {
            int r = i / BN, c = i % BN;
            int gr = k0 + r, gc = col0 + c;
            Bs[r][c] = (gc < N) ? B[(size_t)gr * N + gc] : 0.f;
        }
        __syncthreads();

        #pragma unroll
        for (int kk = 0; kk < BK; kk++) {
            float a[8], b[8];
            #pragma unroll
            for (int i = 0; i < 8; i++) a[i] = As[kk][ty * 8 + i];
            #pragma unroll
            for (int j = 0; j < 8; j++) b[j] = Bs[kk][tx * 8 + j];
            #pragma unroll
            for (int i = 0; i < 8; i++)
                #pragma unroll
                for (int j = 0; j < 8; j++) acc[i][j] = fmaf(a[i], b[j], acc[i][j]);
        }
        __syncthreads();
    }

    #pragma unroll
    for (int i = 0; i < 8; i++) {
        int gr = row0 + ty * 8 + i;
        if (gr >= M) continue;
        #pragma unroll
        for (int j = 0; j < 8; j++) {
            int gc = col0 + tx * 8 + j;
            if (gc >= N) continue;
            size_t idx = (size_t)gr * N + gc;
            float v = acc[i][j];
            if (bias)  v += bias[gc];
            if (accum) v += C[idx];
            if (act == 1) v = eluf(v);
            C[idx] = v;
        }
    }
}

// ---------------------------------------------------------------------------
// b_eff[j] = sum_p bv[p] * Wo[p,j] + bo[j]
// ---------------------------------------------------------------------------
__global__ void beff_kernel(const float* __restrict__ bv,
                            const float* __restrict__ Wo,
                            const float* __restrict__ bo)
{
    int j = blockIdx.x * blockDim.x + threadIdx.x;
    if (j >= DMODEL) return;
    float s = bo[j];
    for (int p = 0; p < PDIM; p++) s = fmaf(bv[p], Wo[(size_t)p * DMODEL + j], s);
    g_beff[j] = s;
}

// ---------------------------------------------------------------------------
// Fused per-row encoder: attn (xe @ Weff + beff), LN1, rank-2 FFN, LN2.
// Also assembles g_flat = [x[b,0,:], x[b,1,:], x[b,2,:], output_row].
// Row 0: output_row = x[0,2,:] (no encoder).
// 16 rows per block, 512 threads (one warp per row for reductions).
// ---------------------------------------------------------------------------
__global__ __launch_bounds__(512)
void row_kernel(const float* __restrict__ x,
                const float* __restrict__ ln1g, const float* __restrict__ ln1b,
                const float* __restrict__ fw1,  const float* __restrict__ fb1,
                const float* __restrict__ fw2,  const float* __restrict__ fb2,
                const float* __restrict__ ln2g, const float* __restrict__ ln2b)
{
    __shared__ float xs[16][DMODEL];   // xe rows, then reused as t1/t2 buffer

    const int tid = threadIdx.x;
    const int r0  = blockIdx.x * 16;

    // Copy x -> flat[0:1200] and stage xe = x[:,2,:] into smem
    for (int i = tid; i < 16 * 1200; i += 512) {
        int r = i / 1200, c = i % 1200;
        int gr = r0 + r;
        float v = x[(size_t)gr * 1200 + c];
        g_flat[(size_t)gr * FLATK + c] = v;
        if (c >= 800) xs[r][c - 800] = v;
    }
    __syncthreads();

    // Row 0 special: flat[0, 1200:1600] = x[0,2,:]
    if (r0 == 0) {
        for (int j = tid; j < DMODEL; j += 512)
            g_flat[1200 + j] = xs[0][j];
    }

    // attn GEMM: thread j computes column j for all 16 rows
    float acc[16];
    if (tid < DMODEL) {
        #pragma unroll
        for (int r = 0; r < 16; r++) acc[r] = 0.f;
        for (int k = 0; k < DMODEL; k++) {
            float w = g_Weff[k * DMODEL + tid];
            #pragma unroll
            for (int r = 0; r < 16; r++) acc[r] = fmaf(xs[r][k], w, acc[r]);
        }
    }
    __syncthreads();
    if (tid < DMODEL) {
        float be = g_beff[tid];
        #pragma unroll
        for (int r = 0; r < 16; r++) xs[r][tid] = xs[r][tid] + acc[r] + be;
    }
    __syncthreads();

    // Warp-per-row: LN1 -> FFN -> LN2 -> write flat[:,1200:1600]
    const int w    = tid / 32;
    const int lane = tid % 32;
    const int gr   = r0 + w;

    float s = 0.f, sq = 0.f;
    for (int j = lane; j < DMODEL; j += 32) {
        float v = xs[w][j]; s += v; sq += v * v;
    }
    #pragma unroll
    for (int o = 16; o > 0; o >>= 1) {
        s  += __shfl_xor_sync(0xffffffffu, s, o);
        sq += __shfl_xor_sync(0xffffffffu, sq, o);
    }
    float m    = s / (float)DMODEL;
    float var  = fmaxf(sq / (float)DMODEL - m * m, 0.f);
    float rstd = rsqrtf(var + 1e-6f);

    float d0 = 0.f, d1 = 0.f;
    for (int j = lane; j < DMODEL; j += 32) {
        float o1 = (xs[w][j] - m) * rstd * ln1g[j] + ln1b[j];
        xs[w][j] = o1;
        d0 = fmaf(o1, fw1[j * 2 + 0], d0);
        d1 = fmaf(o1, fw1[j * 2 + 1], d1);
    }
    #pragma unroll
    for (int o = 16; o > 0; o >>= 1) {
        d0 += __shfl_xor_sync(0xffffffffu, d0, o);
        d1 += __shfl_xor_sync(0xffffffffu, d1, o);
    }
    float h0 = fmaxf(d0 + fb1[0], 0.f);
    float h1 = fmaxf(d1 + fb1[1], 0.f);

    float s2 = 0.f, sq2 = 0.f;
    for (int j = lane; j < DMODEL; j += 32) {
        float t = xs[w][j] + h0 * fw2[j] + h1 * fw2[DMODEL + j] + fb2[j];
        xs[w][j] = t;
        s2 += t; sq2 += t * t;
    }
    #pragma unroll
    for (int o = 16; o > 0; o >>= 1) {
        s2  += __shfl_xor_sync(0xffffffffu, s2, o);
        sq2 += __shfl_xor_sync(0xffffffffu, sq2, o);
    }
    float m2    = s2 / (float)DMODEL;
    float var2  = fmaxf(sq2 / (float)DMODEL - m2 * m2, 0.f);
    float rstd2 = rsqrtf(var2 + 1e-6f);

    if (gr != 0) {
        for (int j = lane; j < DMODEL; j += 32)
            g_flat[(size_t)gr * FLATK + 1200 + j] =
                (xs[w][j] - m2) * rstd2 * ln2g[j] + ln2b[j];
    }
}

// ---------------------------------------------------------------------------
// GRU gate epilogue (h0 = 0):
//   z = sigmoid(xz + B1z); r = sigmoid(xr + B1r); hh = elu(xh + r*B1h)
//   h = (1 - z) * hh     (B0 already added as GEMM bias)
// ---------------------------------------------------------------------------
__global__ void gru_epi_kernel(const float* __restrict__ G,
                               const float* __restrict__ B1,
                               float* __restrict__ x1out, int col_off)
{
    size_t idx = (size_t)blockIdx.x * blockDim.x + threadIdx.x;
    if (idx >= (size_t)NROWS * GUC) return;
    int mrow = (int)(idx / GUC);
    int j    = (int)(idx % GUC);
    size_t base = (size_t)mrow * G3;
    float xz = G[base + j];
    float xr = G[base + GUC + j];
    float xh = G[base + 2 * GUC + j];
    float z  = sigmoidf_(xz + B1[j]);
    float r  = sigmoidf_(xr + B1[GUC + j]);
    float hh = eluf(xh + r * B1[2 * GUC + j]);
    x1out[(size_t)mrow * X1C + col_off + j] = (1.f - z) * hh;
}

// ---------------------------------------------------------------------------
// Launch
// ---------------------------------------------------------------------------
static inline dim3 gemm_grid(int M, int N) {
    return dim3((N + BN - 1) / BN, (M + BM - 1) / BM);
}

extern "C" void kernel_launch(void* const* d_in, const int* in_sizes, int n_in,
                              void* d_out, int out_size)
{
    // Layout detection: dict-insertion order vs reference-signature order.
    // dict:  idx10 = ffn_w1 (800 elems).  sig: idx10 = ln1_b (400 elems).
    const bool dict = (in_sizes[10] == 800);

    const float* x  = (const float*)d_in[0];
    const float* Wv = (const float*)d_in[5];
    const float* bv = (const float*)d_in[6];
    const float* Wo = (const float*)d_in[7];
    const float* bo = (const float*)d_in[8];

    const float *ln1g, *ln1b, *fw1, *fb1, *fw2, *fb2, *ln2g, *ln2b;
    const float *gfk, *gfb, *gbk, *gbb, *d2w, *d2b, *d4w, *d4b, *ow, *ob;
    if (dict) {
        ln1b = (const float*)d_in[9];
        fw1  = (const float*)d_in[10]; fb1 = (const float*)d_in[11];
        fw2  = (const float*)d_in[12]; fb2 = (const float*)d_in[13];
        ln2b = (const float*)d_in[14];
        gfk  = (const float*)d_in[15]; gfb = (const float*)d_in[17];
        gbk  = (const float*)d_in[18]; gbb = (const float*)d_in[20];
        d2w  = (const float*)d_in[21]; d2b = (const float*)d_in[22];
        d4w  = (const float*)d_in[23]; d4b = (const float*)d_in[24];
        ow   = (const float*)d_in[25]; ob  = (const float*)d_in[26];
        ln1g = (const float*)d_in[27]; ln2g = (const float*)d_in[28];
    } else {
        ln1g = (const float*)d_in[9];  ln1b = (const float*)d_in[10];
        fw1  = (const float*)d_in[11]; fb1 = (const float*)d_in[12];
        fw2  = (const float*)d_in[13]; fb2 = (const float*)d_in[14];
        ln2g = (const float*)d_in[15]; ln2b = (const float*)d_in[16];
        gfk  = (const float*)d_in[17]; gfb = (const float*)d_in[19];
        gbk  = (const float*)d_in[20]; gbb = (const float*)d_in[22];
        d2w  = (const float*)d_in[23]; d2b = (const float*)d_in[24];
        d4w  = (const float*)d_in[25]; d4b = (const float*)d_in[26];
        ow   = (const float*)d_in[27]; ob  = (const float*)d_in[28];
    }
    float* out = (float*)d_out;

    float *Weff, *flat, *G, *x1, *x3, *x5;
    cudaGetSymbolAddress((void**)&Weff, g_Weff);
    cudaGetSymbolAddress((void**)&flat, g_flat);
    cudaGetSymbolAddress((void**)&G,    g_G);
    cudaGetSymbolAddress((void**)&x1,   g_x1);
    cudaGetSymbolAddress((void**)&x3,   g_x3);
    cudaGetSymbolAddress((void**)&x5,   g_x5);

    // 1) Effective attention matrix: Weff = Wv_flat(400x6400) @ Wo_flat(6400x400)
    gemm_kernel<<<gemm_grid(DMODEL, DMODEL), 256>>>(Wv, Wo, nullptr, Weff,
                                                    DMODEL, DMODEL, PDIM, 0, 0);
    beff_kernel<<<2, 256>>>(bv, Wo, bo);

    // 2) Fused encoder + flat assembly
    row_kernel<<<NROWS / 16, 512>>>(x, ln1g, ln1b, fw1, fb1, fw2, fb2, ln2g, ln2b);

    // 3) Forward GRU: G = flat @ gru_fk + B0 ; gates -> x1[:, 0:1800]
    gemm_kernel<<<gemm_grid(NROWS, G3), 256>>>(flat, gfk, gfb, G,
                                               NROWS, G3, FLATK, 0, 0);
    {
        size_t tot = (size_t)NROWS * GUC;
        gru_epi_kernel<<<(unsigned)((tot + 255) / 256), 256>>>(G, gfb + G3, x1, 0);
    }
    // 4) Backward GRU -> x1[:, 1800:3600]
    gemm_kernel<<<gemm_grid(NROWS, G3), 256>>>(flat, gbk, gbb, G,
                                               NROWS, G3, FLATK, 0, 0);
    {
        size_t tot = (size_t)NROWS * GUC;
        gru_epi_kernel<<<(unsigned)((tot + 255) / 256), 256>>>(G, gbb + G3, x1, GUC);
    }

    // 5) x3 = elu(x1 @ d2_w + d2_b)
    gemm_kernel<<<gemm_grid(NROWS, GUC), 256>>>(x1, d2w, d2b, x3,
                                                NROWS, GUC, X1C, 1, 0);
    // 6) x5 = elu(x3 @ d4_w + d4_b)
    gemm_kernel<<<gemm_grid(NROWS, GUC), 256>>>(x3, d4w, d4b, x5,
                                                NROWS, GUC, GUC, 1, 0);

    // 7) out = x1 @ ow[0:3600] + x3 @ ow[3600:5400] + x5 @ ow[5400:7200] + ob
    gemm_kernel<<<gemm_grid(NROWS, OUTC), 256>>>(x1, ow, ob, out,
                                                 NROWS, OUTC, X1C, 0, 0);
    gemm_kernel<<<gemm_grid(NROWS, OUTC), 256>>>(x3, ow + (size_t)X1C * OUTC,
                                                 nullptr, out,
                                                 NROWS, OUTC, GUC, 0, 1);
    gemm_kernel<<<gemm_grid(NROWS, OUTC), 256>>>(x5, ow + (size_t)G3 * OUTC,
                                                 nullptr, out,
                                                 NROWS, OUTC, GUC, 0, 1);
}

// round 3
// speedup vs baseline: 2.7162x; 2.7162x over previous
#include <cuda_runtime.h>
#include <cuda_bf16.h>
#include <math.h>
#include <stdint.h>

// ---------------------------------------------------------------------------
// Constants
// ---------------------------------------------------------------------------
#define NROWS   16384
#define DMODEL  400
#define PDIM    6400
#define FLATK   1600
#define FLATE   4800      // 3*FLATK (bf16 split expansion)
#define G3      5400
#define GUC     1800
#define X1C     3600
#define CATE    21600     // 3*(3600+1800+1800)
#define OUTC    140
#define OWPAD   160

// ---------------------------------------------------------------------------
// Scratch (device globals)
// ---------------------------------------------------------------------------
__device__ __align__(256) float g_Weff[DMODEL * DMODEL];
__device__ __align__(256) float g_beff[DMODEL];
__device__ __align__(256) __nv_bfloat16 g_flatE[(size_t)NROWS * FLATE];
__device__ __align__(256) __nv_bfloat16 g_gfkE[(size_t)FLATE * G3];
__device__ __align__(256) __nv_bfloat16 g_gbkE[(size_t)FLATE * G3];
__device__ __align__(256) __nv_bfloat16 g_d2wE[(size_t)3 * X1C * GUC];
__device__ __align__(256) __nv_bfloat16 g_d4wE[(size_t)3 * GUC * GUC];
__device__ __align__(256) __nv_bfloat16 g_owE[(size_t)CATE * OWPAD];
__device__ __align__(256) float g_G[(size_t)NROWS * G3];
__device__ __align__(256) __nv_bfloat16 g_catE[(size_t)NROWS * CATE];

__device__ __forceinline__ float eluf(float v)      { return v > 0.f ? v : expm1f(v); }
__device__ __forceinline__ float sigmoidf_(float v) { return 1.f / (1.f + expf(-v)); }
__device__ __forceinline__ void split_bf16(float v, __nv_bfloat16& h, __nv_bfloat16& l) {
    h = __float2bfloat16(v);
    l = __float2bfloat16(v - __bfloat162float(h));
}

// ---------------------------------------------------------------------------
// bf16 tensor-core GEMM: C(MxN) = A(MxK) @ B(KxN)  (fp32 accumulate)
//   mode 0: Cf[gr*ldc+gc] = acc + bias[gc]          (gc < Nout)
//   mode 2: v = elu(acc + bias[gc]); split -> hi1/hi2/lo at gr*lds+gc
// 128x128 tile, BK=32, 256 threads, cp.async double buffer, ldmatrix + mma.
// ---------------------------------------------------------------------------
#define TBM 128
#define TBN 128
#define TBK 32
#define SAP 40    // As row stride (halves): 80B rows -> conflict-free ldmatrix
#define SBP 136   // Bs row stride (halves): 272B rows

__global__ __launch_bounds__(256)
void mma_gemm(const __nv_bfloat16* __restrict__ A, const __nv_bfloat16* __restrict__ B,
              const float* __restrict__ bias,
              int M, int N, int K, int lda, int ldb,
              int mode, float* __restrict__ Cf, int ldc,
              __nv_bfloat16* __restrict__ hi1, __nv_bfloat16* __restrict__ hi2,
              __nv_bfloat16* __restrict__ lo, int lds, int Nout)
{
    __shared__ __nv_bfloat16 sA[2][TBM * SAP];
    __shared__ __nv_bfloat16 sB[2][TBK * SBP];

    const int tid  = threadIdx.x;
    const int lane = tid & 31;
    const int wid  = tid >> 5;
    const int wm   = wid >> 2;                 // 0..1
    const int wn   = wid & 3;                  // 0..3
    const int r0w  = wm * 64;
    const int n0w  = wn * 32;
    const int row0 = blockIdx.y * TBM;
    const int col0 = blockIdx.x * TBN;

    float acc[4][4][4];
    #pragma unroll
    for (int i = 0; i < 4; i++)
        #pragma unroll
        for (int j = 0; j < 4; j++)
            #pragma unroll
            for (int q = 0; q < 4; q++) acc[i][j][q] = 0.f;

    const int nt = (K + TBK - 1) / TBK;

    auto load_tiles = [&](int stage, int kt) {
        const int k0 = kt * TBK;
        // A tile: 128 x 32 halves = 512 x 16B chunks
        #pragma unroll
        for (int c = 0; c < 2; c++) {
            int chunk = tid + c * 256;
            int r  = chunk >> 2;
            int cc = chunk & 3;
            int kk = k0 + cc * 8;
            bool valid = (kk < K);
            const __nv_bfloat16* gp = valid ? (A + (size_t)(row0 + r) * lda + kk) : A;
            uint32_t sa = (uint32_t)__cvta_generic_to_shared(&sA[stage][r * SAP + cc * 8]);
            int sz = valid ? 16 : 0;
            asm volatile("cp.async.cg.shared.global [%0], [%1], 16, %2;\n"
                         :: "r"(sa), "l"(gp), "r"(sz) : "memory");
        }
        // B tile: 32 x 128 halves = 512 x 16B chunks
        #pragma unroll
        for (int c = 0; c < 2; c++) {
            int chunk = tid + c * 256;
            int r  = chunk >> 4;
            int cc = chunk & 15;
            int nn = col0 + cc * 8;
            bool valid = (k0 + r < K) && (nn < N);
            const __nv_bfloat16* gp = valid ? (B + (size_t)(k0 + r) * ldb + nn) : B;
            uint32_t sa = (uint32_t)__cvta_generic_to_shared(&sB[stage][r * SBP + cc * 8]);
            int sz = valid ? 16 : 0;
            asm volatile("cp.async.cg.shared.global [%0], [%1], 16, %2;\n"
                         :: "r"(sa), "l"(gp), "r"(sz) : "memory");
        }
        asm volatile("cp.async.commit_group;\n" ::: "memory");
    };

    int buf = 0;
    load_tiles(0, 0);

    for (int kt = 0; kt < nt; kt++) {
        asm volatile("cp.async.wait_group 0;\n" ::: "memory");
        __syncthreads();
        if (kt + 1 < nt) load_tiles(buf ^ 1, kt + 1);

        #pragma unroll
        for (int ks = 0; ks < 2; ks++) {
            uint32_t a[4][4];
            const int arow = lane & 15;
            const int acol = ks * 16 + (lane >> 4) * 8;
            #pragma unroll
            for (int mi = 0; mi < 4; mi++) {
                uint32_t addr = (uint32_t)__cvta_generic_to_shared(
                    &sA[buf][(r0w + mi * 16 + arow) * SAP + acol]);
                asm volatile("ldmatrix.sync.aligned.m8n8.x4.shared.b16 {%0,%1,%2,%3}, [%4];\n"
                             : "=r"(a[mi][0]), "=r"(a[mi][1]), "=r"(a[mi][2]), "=r"(a[mi][3])
                             : "r"(addr));
            }
            uint32_t b[2][4];
            const int brow = ks * 16 + (lane & 15);
            #pragma unroll
            for (int nj2 = 0; nj2 < 2; nj2++) {
                int bcol = n0w + nj2 * 16 + (lane >> 4) * 8;
                uint32_t addr = (uint32_t)__cvta_generic_to_shared(
                    &sB[buf][brow * SBP + bcol]);
                asm volatile("ldmatrix.sync.aligned.m8n8.x4.trans.shared.b16 {%0,%1,%2,%3}, [%4];\n"
                             : "=r"(b[nj2][0]), "=r"(b[nj2][1]), "=r"(b[nj2][2]), "=r"(b[nj2][3])
                             : "r"(addr));
            }
            #pragma unroll
            for (int mi = 0; mi < 4; mi++) {
                #pragma unroll
                for (int nj = 0; nj < 4; nj++) {
                    uint32_t b0 = b[nj >> 1][(nj & 1) * 2];
                    uint32_t b1 = b[nj >> 1][(nj & 1) * 2 + 1];
                    asm volatile(
                        "mma.sync.aligned.m16n8k16.row.col.f32.bf16.bf16.f32 "
                        "{%0,%1,%2,%3}, {%4,%5,%6,%7}, {%8,%9}, {%0,%1,%2,%3};\n"
                        : "+f"(acc[mi][nj][0]), "+f"(acc[mi][nj][1]),
                          "+f"(acc[mi][nj][2]), "+f"(acc[mi][nj][3])
                        : "r"(a[mi][0]), "r"(a[mi][1]), "r"(a[mi][2]), "r"(a[mi][3]),
                          "r"(b0), "r"(b1));
                }
            }
        }
        buf ^= 1;
    }

    // Epilogue
    #pragma unroll
    for (int mi = 0; mi < 4; mi++) {
        #pragma unroll
        for (int half = 0; half < 2; half++) {
            int gr = row0 + r0w + mi * 16 + (lane >> 2) + half * 8;
            #pragma unroll
            for (int nj = 0; nj < 4; nj++) {
                #pragma unroll
                for (int q = 0; q < 2; q++) {
                    int gc = col0 + n0w + nj * 8 + (lane & 3) * 2 + q;
                    if (gc >= Nout) continue;
                    float v = acc[mi][nj][half * 2 + q];
                    if (bias) v += bias[gc];
                    if (mode == 0) {
                        Cf[(size_t)gr * ldc + gc] = v;
                    } else {
                        v = eluf(v);
                        __nv_bfloat16 h, l;
                        split_bf16(v, h, l);
                        size_t o = (size_t)gr * lds + gc;
                        hi1[o] = h; hi2[o] = h; lo[o] = l;
                    }
                }
            }
        }
    }
}

// ---------------------------------------------------------------------------
// fp32 SIMT GEMM (only for the tiny 400x400x6400 Weff precompute)
// ---------------------------------------------------------------------------
#define BM 128
#define BN 128
#define BK 8
__global__ __launch_bounds__(256)
void gemm_kernel(const float* __restrict__ A, const float* __restrict__ B,
                 float* __restrict__ C, int M, int N, int K)
{
    __shared__ float As[BK][BM];
    __shared__ float Bs[BK][BN];
    const int tid = threadIdx.x;
    const int tx  = tid % 16;
    const int ty  = tid / 16;
    const int row0 = blockIdx.y * BM;
    const int col0 = blockIdx.x * BN;

    float acc[8][8];
    #pragma unroll
    for (int i = 0; i < 8; i++)
        #pragma unroll
        for (int j = 0; j < 8; j++) acc[i][j] = 0.f;

    for (int k0 = 0; k0 < K; k0 += BK) {
        #pragma unroll
        for (int i = tid; i < BM * BK; i += 256) {
            int r = i / BK, c = i % BK;
            int gr = row0 + r;
            As[c][r] = (gr < M) ? A[(size_t)gr * K + k0 + c] : 0.f;
        }
        #pragma unroll
        for (int i = tid; i < BK * BN; i += 256) {
            int r = i / BN, c = i % BN;
            int gc = col0 + c;
            Bs[r][c] = (gc < N) ? B[(size_t)(k0 + r) * N + gc] : 0.f;
        }
        __syncthreads();
        #pragma unroll
        for (int kk = 0; kk < BK; kk++) {
            float a[8], b[8];
            #pragma unroll
            for (int i = 0; i < 8; i++) a[i] = As[kk][ty * 8 + i];
            #pragma unroll
            for (int j = 0; j < 8; j++) b[j] = Bs[kk][tx * 8 + j];
            #pragma unroll
            for (int i = 0; i < 8; i++)
                #pragma unroll
                for (int j = 0; j < 8; j++) acc[i][j] = fmaf(a[i], b[j], acc[i][j]);
        }
        __syncthreads();
    }
    #pragma unroll
    for (int i = 0; i < 8; i++) {
        int gr = row0 + ty * 8 + i;
        if (gr >= M) continue;
        #pragma unroll
        for (int j = 0; j < 8; j++) {
            int gc = col0 + tx * 8 + j;
            if (gc < N) C[(size_t)gr * N + gc] = acc[i][j];
        }
    }
}

__global__ void beff_kernel(const float* __restrict__ bv,
                            const float* __restrict__ Wo,
                            const float* __restrict__ bo)
{
    int j = blockIdx.x * blockDim.x + threadIdx.x;
    if (j >= DMODEL) return;
    float s = bo[j];
    for (int p = 0; p < PDIM; p++) s = fmaf(bv[p], Wo[(size_t)p * DMODEL + j], s);
    g_beff[j] = s;
}

// ---------------------------------------------------------------------------
// Weight split: src(K0 x N) fp32 -> dst bf16 (ld=Npad), hi rows duplicated at
// off_hi1/off_hi2, lo rows at off_lo; cols >= N zero-padded.
// ---------------------------------------------------------------------------
__global__ void split_w(const float* __restrict__ src, __nv_bfloat16* __restrict__ dst,
                        int K0, int N, int Npad,
                        int off_hi1, int off_hi2, int off_lo)
{
    size_t idx = (size_t)blockIdx.x * blockDim.x + threadIdx.x;
    if (idx >= (size_t)K0 * Npad) return;
    int k = (int)(idx / Npad);
    int n = (int)(idx % Npad);
    float v = (n < N) ? src[(size_t)k * N + n] : 0.f;
    __nv_bfloat16 h, l;
    split_bf16(v, h, l);
    dst[(size_t)(off_hi1 + k) * Npad + n] = h;
    dst[(size_t)(off_hi2 + k) * Npad + n] = h;
    dst[(size_t)(off_lo  + k) * Npad + n] = l;
}

// ---------------------------------------------------------------------------
// Fused encoder: attn (xe@Weff+beff), LN1, rank-2 FFN, LN2; writes split
// bf16 flatE = [hi(1600) | lo(1600) | hi(1600)] per row.
// ---------------------------------------------------------------------------
__global__ __launch_bounds__(512)
void row_kernel(const float* __restrict__ x,
                const float* __restrict__ ln1g, const float* __restrict__ ln1b,
                const float* __restrict__ fw1,  const float* __restrict__ fb1,
                const float* __restrict__ fw2,  const float* __restrict__ fb2,
                const float* __restrict__ ln2g, const float* __restrict__ ln2b)
{
    __shared__ float xs[16][DMODEL];
    const int tid = threadIdx.x;
    const int r0  = blockIdx.x * 16;

    for (int i = tid; i < 16 * 1200; i += 512) {
        int r = i / 1200, c = i % 1200;
        int gr = r0 + r;
        float v = x[(size_t)gr * 1200 + c];
        __nv_bfloat16 h, l;
        split_bf16(v, h, l);
        size_t base = (size_t)gr * FLATE;
        g_flatE[base + c]        = h;
        g_flatE[base + 1600 + c] = l;
        g_flatE[base + 3200 + c] = h;
        if (c >= 800) xs[r][c - 800] = v;
    }
    __syncthreads();

    if (r0 == 0) {
        for (int j = tid; j < DMODEL; j += 512) {
            __nv_bfloat16 h, l;
            split_bf16(xs[0][j], h, l);
            g_flatE[1200 + j] = h;
            g_flatE[2800 + j] = l;
            g_flatE[4400 + j] = h;
        }
    }

    // attn: thread j computes column j for all 16 rows
    float acc[16];
    if (tid < DMODEL) {
        #pragma unroll
        for (int r = 0; r < 16; r++) acc[r] = 0.f;
        for (int k = 0; k < DMODEL; k++) {
            float w = g_Weff[k * DMODEL + tid];
            #pragma unroll
            for (int r = 0; r < 16; r++) acc[r] = fmaf(xs[r][k], w, acc[r]);
        }
    }
    __syncthreads();
    if (tid < DMODEL) {
        float be = g_beff[tid];
        #pragma unroll
        for (int r = 0; r < 16; r++) xs[r][tid] = xs[r][tid] + acc[r] + be;
    }
    __syncthreads();

    const int w    = tid / 32;
    const int lane = tid % 32;
    const int gr   = r0 + w;

    float s = 0.f, sq = 0.f;
    for (int j = lane; j < DMODEL; j += 32) { float v = xs[w][j]; s += v; sq += v * v; }
    #pragma unroll
    for (int o = 16; o > 0; o >>= 1) {
        s  += __shfl_xor_sync(0xffffffffu, s, o);
        sq += __shfl_xor_sync(0xffffffffu, sq, o);
    }
    float m    = s / (float)DMODEL;
    float var  = fmaxf(sq / (float)DMODEL - m * m, 0.f);
    float rstd = rsqrtf(var + 1e-6f);

    float d0 = 0.f, d1 = 0.f;
    for (int j = lane; j < DMODEL; j += 32) {
        float o1 = (xs[w][j] - m) * rstd * ln1g[j] + ln1b[j];
        xs[w][j] = o1;
        d0 = fmaf(o1, fw1[j * 2 + 0], d0);
        d1 = fmaf(o1, fw1[j * 2 + 1], d1);
    }
    #pragma unroll
    for (int o = 16; o > 0; o >>= 1) {
        d0 += __shfl_xor_sync(0xffffffffu, d0, o);
        d1 += __shfl_xor_sync(0xffffffffu, d1, o);
    }
    float h0 = fmaxf(d0 + fb1[0], 0.f);
    float h1 = fmaxf(d1 + fb1[1], 0.f);

    float s2 = 0.f, sq2 = 0.f;
    for (int j = lane; j < DMODEL; j += 32) {
        float t = xs[w][j] + h0 * fw2[j] + h1 * fw2[DMODEL + j] + fb2[j];
        xs[w][j] = t;
        s2 += t; sq2 += t * t;
    }
    #pragma unroll
    for (int o = 16; o > 0; o >>= 1) {
        s2  += __shfl_xor_sync(0xffffffffu, s2, o);
        sq2 += __shfl_xor_sync(0xffffffffu, sq2, o);
    }
    float m2    = s2 / (float)DMODEL;
    float var2  = fmaxf(sq2 / (float)DMODEL - m2 * m2, 0.f);
    float rstd2 = rsqrtf(var2 + 1e-6f);

    if (gr != 0) {
        for (int j = lane; j < DMODEL; j += 32) {
            float v = (xs[w][j] - m2) * rstd2 * ln2g[j] + ln2b[j];
            __nv_bfloat16 h, l;
            split_bf16(v, h, l);
            size_t base = (size_t)gr * FLATE;
            g_flatE[base + 1200 + j] = h;
            g_flatE[base + 2800 + j] = l;
            g_flatE[base + 4400 + j] = h;
        }
    }
}

// ---------------------------------------------------------------------------
// GRU gate epilogue (h0=0); writes split bf16 into catE at x1 columns.
// ---------------------------------------------------------------------------
__global__ void gru_epi_kernel(const float* __restrict__ G,
                               const float* __restrict__ B1, int coloff)
{
    size_t idx = (size_t)blockIdx.x * blockDim.x + threadIdx.x;
    if (idx >= (size_t)NROWS * GUC) return;
    int mrow = (int)(idx / GUC);
    int j    = (int)(idx % GUC);
    size_t base = (size_t)mrow * G3;
    float xz = G[base + j];
    float xr = G[base + GUC + j];
    float xh = G[base + 2 * GUC + j];
    float z  = sigmoidf_(xz + B1[j]);
    float r  = sigmoidf_(xr + B1[GUC + j]);
    float hh = eluf(xh + r * B1[2 * GUC + j]);
    float h  = (1.f - z) * hh;

    __nv_bfloat16 hi, lo;
    split_bf16(h, hi, lo);
    int c = coloff + j;
    size_t o = (size_t)mrow * CATE;
    g_catE[o + c]        = hi;
    g_catE[o + 3600 + c] = lo;
    g_catE[o + 7200 + c] = hi;
}

// ---------------------------------------------------------------------------
// Launch
// ---------------------------------------------------------------------------
extern "C" void kernel_launch(void* const* d_in, const int* in_sizes, int n_in,
                              void* d_out, int out_size)
{
    const bool dict = (in_sizes[10] == 800);

    const float* x  = (const float*)d_in[0];
    const float* Wv = (const float*)d_in[5];
    const float* bv = (const float*)d_in[6];
    const float* Wo = (const float*)d_in[7];
    const float* bo = (const float*)d_in[8];

    const float *ln1g, *ln1b, *fw1, *fb1, *fw2, *fb2, *ln2g, *ln2b;
    const float *gfk, *gfb, *gbk, *gbb, *d2w, *d2b, *d4w, *d4b, *ow, *ob;
    if (dict) {
        ln1b = (const float*)d_in[9];
        fw1  = (const float*)d_in[10]; fb1 = (const float*)d_in[11];
        fw2  = (const float*)d_in[12]; fb2 = (const float*)d_in[13];
        ln2b = (const float*)d_in[14];
        gfk  = (const float*)d_in[15]; gfb = (const float*)d_in[17];
        gbk  = (const float*)d_in[18]; gbb = (const float*)d_in[20];
        d2w  = (const float*)d_in[21]; d2b = (const float*)d_in[22];
        d4w  = (const float*)d_in[23]; d4b = (const float*)d_in[24];
        ow   = (const float*)d_in[25]; ob  = (const float*)d_in[26];
        ln1g = (const float*)d_in[27]; ln2g = (const float*)d_in[28];
    } else {
        ln1g = (const float*)d_in[9];  ln1b = (const float*)d_in[10];
        fw1  = (const float*)d_in[11]; fb1 = (const float*)d_in[12];
        fw2  = (const float*)d_in[13]; fb2 = (const float*)d_in[14];
        ln2g = (const float*)d_in[15]; ln2b = (const float*)d_in[16];
        gfk  = (const float*)d_in[17]; gfb = (const float*)d_in[19];
        gbk  = (const float*)d_in[20]; gbb = (const float*)d_in[22];
        d2w  = (const float*)d_in[23]; d2b = (const float*)d_in[24];
        d4w  = (const float*)d_in[25]; d4b = (const float*)d_in[26];
        ow   = (const float*)d_in[27]; ob  = (const float*)d_in[28];
    }
    float* out = (float*)d_out;

    float *Weff, *G;
    __nv_bfloat16 *flatE, *gfkE, *gbkE, *d2wE, *d4wE, *owE, *catE;
    cudaGetSymbolAddress((void**)&Weff,  g_Weff);
    cudaGetSymbolAddress((void**)&G,     g_G);
    cudaGetSymbolAddress((void**)&flatE, g_flatE);
    cudaGetSymbolAddress((void**)&gfkE,  g_gfkE);
    cudaGetSymbolAddress((void**)&gbkE,  g_gbkE);
    cudaGetSymbolAddress((void**)&d2wE,  g_d2wE);
    cudaGetSymbolAddress((void**)&d4wE,  g_d4wE);
    cudaGetSymbolAddress((void**)&owE,   g_owE);
    cudaGetSymbolAddress((void**)&catE,  g_catE);

    // 1) Attention collapse precompute (fp32, tiny)
    gemm_kernel<<<dim3(4, 4), 256>>>(Wv, Wo, Weff, DMODEL, DMODEL, PDIM);
    beff_kernel<<<2, 256>>>(bv, Wo, bo);

    // 2) Weight splits (hi;hi;lo row-block expansion)
    {
        auto launch_split = [&](const float* s, __nv_bfloat16* d, int K0, int N, int Np,
                                int o1, int o2, int o3) {
            size_t tot = (size_t)K0 * Np;
            split_w<<<(unsigned)((tot + 255) / 256), 256>>>(s, d, K0, N, Np, o1, o2, o3);
        };
        launch_split(gfk, gfkE, FLATK, G3, G3, 0, FLATK, 2 * FLATK);
        launch_split(gbk, gbkE, FLATK, G3, G3, 0, FLATK, 2 * FLATK);
        launch_split(d2w, d2wE, X1C, GUC, GUC, 0, X1C, 2 * X1C);
        launch_split(d4w, d4wE, GUC, GUC, GUC, 0, GUC, 2 * GUC);
        launch_split(ow,                      owE, X1C, OUTC, OWPAD, 0,     X1C,   7200);
        launch_split(ow + (size_t)X1C * OUTC, owE, GUC, OUTC, OWPAD, 10800, 12600, 14400);
        launch_split(ow + (size_t)G3  * OUTC, owE, GUC, OUTC, OWPAD, 16200, 18000, 19800);
    }

    // 3) Fused encoder -> flatE
    row_kernel<<<NROWS / 16, 512>>>(x, ln1g, ln1b, fw1, fb1, fw2, fb2, ln2g, ln2b);

    const unsigned epi_blocks = (unsigned)(((size_t)NROWS * GUC + 255) / 256);

    // 4) Forward GRU
    mma_gemm<<<dim3((G3 + TBN - 1) / TBN, NROWS / TBM), 256>>>(
        flatE, gfkE, gfb, NROWS, G3, FLATE, FLATE, G3,
        0, G, G3, nullptr, nullptr, nullptr, 0, G3);
    gru_epi_kernel<<<epi_blocks, 256>>>(G, gfb + G3, 0);

    // 5) Backward GRU
    mma_gemm<<<dim3((G3 + TBN - 1) / TBN, NROWS / TBM), 256>>>(
        flatE, gbkE, gbb, NROWS, G3, FLATE, FLATE, G3,
        0, G, G3, nullptr, nullptr, nullptr, 0, G3);
    gru_epi_kernel<<<epi_blocks, 256>>>(G, gbb + G3, GUC);

    // 6) x3 = elu(x1 @ d2w + d2b) -> catE cols [10800,16200)
    mma_gemm<<<dim3((GUC + TBN - 1) / TBN, NROWS / TBM), 256>>>(
        catE, d2wE, d2b, NROWS, GUC, 3 * X1C, CATE, GUC,
        2, nullptr, 0, catE + 10800, catE + 14400, catE + 12600, CATE, GUC);

    // 7) x5 = elu(x3 @ d4w + d4b) -> catE cols [16200,21600)
    mma_gemm<<<dim3((GUC + TBN - 1) / TBN, NROWS / TBM), 256>>>(
        catE + 10800, d4wE, d4b, NROWS, GUC, 3 * GUC, CATE, GUC,
        2, nullptr, 0, catE + 16200, catE + 19800, catE + 18000, CATE, GUC);

    // 8) out = cat @ ow + ob  (single K=21600 GEMM)
    mma_gemm<<<dim3((OWPAD + TBN - 1) / TBN, NROWS / TBM), 256>>>(
        catE, owE, ob, NROWS, OWPAD, CATE, CATE, OWPAD,
        0, out, OUTC, nullptr, nullptr, nullptr, 0, OUTC);
}

// round 4
// speedup vs baseline: 2.7203x; 1.0015x over previous
#include <cuda_runtime.h>
#include <cuda_bf16.h>
#include <math.h>
#include <stdint.h>

// ---------------------------------------------------------------------------
// Constants
// ---------------------------------------------------------------------------
#define NROWS   16384
#define DMODEL  400
#define PDIM    6400
#define FLATK   1600
#define FLATE   4800      // 3*FLATK (bf16 split expansion)
#define G3      5400
#define GUC     1800
#define X1C     3600
#define CATE    21600     // 3*(3600+1800+1800)
#define OUTC    140
#define OWPAD   160

// ---------------------------------------------------------------------------
// Scratch (device globals)
// ---------------------------------------------------------------------------
__device__ __align__(256) float g_Weff[DMODEL * DMODEL];
__device__ __align__(256) float g_beff[DMODEL];
__device__ __align__(256) __nv_bfloat16 g_flatE[(size_t)NROWS * FLATE];
__device__ __align__(256) __nv_bfloat16 g_gfkE[(size_t)FLATE * G3];
__device__ __align__(256) __nv_bfloat16 g_gbkE[(size_t)FLATE * G3];
__device__ __align__(256) __nv_bfloat16 g_d2wE[(size_t)3 * X1C * GUC];
__device__ __align__(256) __nv_bfloat16 g_d4wE[(size_t)3 * GUC * GUC];
__device__ __align__(256) __nv_bfloat16 g_owE[(size_t)CATE * OWPAD];
__device__ __align__(256) float g_G[(size_t)NROWS * G3];
__device__ __align__(256) __nv_bfloat16 g_catE[(size_t)NROWS * CATE];

__device__ __forceinline__ float eluf(float v)      { return v > 0.f ? v : expm1f(v); }
__device__ __forceinline__ float sigmoidf_(float v) { return 1.f / (1.f + expf(-v)); }
__device__ __forceinline__ void split_bf16(float v, __nv_bfloat16& h, __nv_bfloat16& l) {
    h = __float2bfloat16(v);
    l = __float2bfloat16(v - __bfloat162float(h));
}

// ---------------------------------------------------------------------------
// bf16 tensor-core GEMM: C(MxN) = A(MxK) @ B(KxN)  (fp32 accumulate)
//   mode 0: Cf[gr*ldc+gc] = acc + bias[gc]          (gc < Nout)
//   mode 2: v = elu(acc + bias[gc]); split -> hi1/hi2/lo at gr*lds+gc
// 128x128 tile, BK=32, 256 threads, cp.async double buffer, ldmatrix + mma.
// ---------------------------------------------------------------------------
#define TBM 128
#define TBN 128
#define TBK 32
#define SAP 40    // As row stride (halves): 80B rows -> conflict-free ldmatrix
#define SBP 136   // Bs row stride (halves): 272B rows

__global__ __launch_bounds__(256)
void mma_gemm(const __nv_bfloat16* __restrict__ A, const __nv_bfloat16* __restrict__ B,
              const float* __restrict__ bias,
              int M, int N, int K, int lda, int ldb,
              int mode, float* __restrict__ Cf, int ldc,
              __nv_bfloat16* __restrict__ hi1, __nv_bfloat16* __restrict__ hi2,
              __nv_bfloat16* __restrict__ lo, int lds, int Nout)
{
    __shared__ __nv_bfloat16 sA[2][TBM * SAP];
    __shared__ __nv_bfloat16 sB[2][TBK * SBP];

    const int tid  = threadIdx.x;
    const int lane = tid & 31;
    const int wid  = tid >> 5;
    const int wm   = wid >> 2;                 // 0..1
    const int wn   = wid & 3;                  // 0..3
    const int r0w  = wm * 64;
    const int n0w  = wn * 32;
    const int row0 = blockIdx.y * TBM;
    const int col0 = blockIdx.x * TBN;

    float acc[4][4][4];
    #pragma unroll
    for (int i = 0; i < 4; i++)
        #pragma unroll
        for (int j = 0; j < 4; j++)
            #pragma unroll
            for (int q = 0; q < 4; q++) acc[i][j][q] = 0.f;

    const int nt = (K + TBK - 1) / TBK;

    auto load_tiles = [&](int stage, int kt) {
        const int k0 = kt * TBK;
        // A tile: 128 x 32 halves = 512 x 16B chunks
        #pragma unroll
        for (int c = 0; c < 2; c++) {
            int chunk = tid + c * 256;
            int r  = chunk >> 2;
            int cc = chunk & 3;
            int kk = k0 + cc * 8;
            bool valid = (kk < K);
            const __nv_bfloat16* gp = valid ? (A + (size_t)(row0 + r) * lda + kk) : A;
            uint32_t sa = (uint32_t)__cvta_generic_to_shared(&sA[stage][r * SAP + cc * 8]);
            int sz = valid ? 16 : 0;
            asm volatile("cp.async.cg.shared.global [%0], [%1], 16, %2;\n"
                         :: "r"(sa), "l"(gp), "r"(sz) : "memory");
        }
        // B tile: 32 x 128 halves = 512 x 16B chunks
        #pragma unroll
        for (int c = 0; c < 2; c++) {
            int chunk = tid + c * 256;
            int r  = chunk >> 4;
            int cc = chunk & 15;
            int nn = col0 + cc * 8;
            bool valid = (k0 + r < K) && (nn < N);
            const __nv_bfloat16* gp = valid ? (B + (size_t)(k0 + r) * ldb + nn) : B;
            uint32_t sa = (uint32_t)__cvta_generic_to_shared(&sB[stage][r * SBP + cc * 8]);
            int sz = valid ? 16 : 0;
            asm volatile("cp.async.cg.shared.global [%0], [%1], 16, %2;\n"
                         :: "r"(sa), "l"(gp), "r"(sz) : "memory");
        }
        asm volatile("cp.async.commit_group;\n" ::: "memory");
    };

    int buf = 0;
    load_tiles(0, 0);

    for (int kt = 0; kt < nt; kt++) {
        asm volatile("cp.async.wait_group 0;\n" ::: "memory");
        __syncthreads();
        if (kt + 1 < nt) load_tiles(buf ^ 1, kt + 1);

        #pragma unroll
        for (int ks = 0; ks < 2; ks++) {
            uint32_t a[4][4];
            const int arow = lane & 15;
            const int acol = ks * 16 + (lane >> 4) * 8;
            #pragma unroll
            for (int mi = 0; mi < 4; mi++) {
                uint32_t addr = (uint32_t)__cvta_generic_to_shared(
                    &sA[buf][(r0w + mi * 16 + arow) * SAP + acol]);
                asm volatile("ldmatrix.sync.aligned.m8n8.x4.shared.b16 {%0,%1,%2,%3}, [%4];\n"
                             : "=r"(a[mi][0]), "=r"(a[mi][1]), "=r"(a[mi][2]), "=r"(a[mi][3])
                             : "r"(addr));
            }
            uint32_t b[2][4];
            const int brow = ks * 16 + (lane & 15);
            #pragma unroll
            for (int nj2 = 0; nj2 < 2; nj2++) {
                int bcol = n0w + nj2 * 16 + (lane >> 4) * 8;
                uint32_t addr = (uint32_t)__cvta_generic_to_shared(
                    &sB[buf][brow * SBP + bcol]);
                asm volatile("ldmatrix.sync.aligned.m8n8.x4.trans.shared.b16 {%0,%1,%2,%3}, [%4];\n"
                             : "=r"(b[nj2][0]), "=r"(b[nj2][1]), "=r"(b[nj2][2]), "=r"(b[nj2][3])
                             : "r"(addr));
            }
            #pragma unroll
            for (int mi = 0; mi < 4; mi++) {
                #pragma unroll
                for (int nj = 0; nj < 4; nj++) {
                    uint32_t b0 = b[nj >> 1][(nj & 1) * 2];
                    uint32_t b1 = b[nj >> 1][(nj & 1) * 2 + 1];
                    asm volatile(
                        "mma.sync.aligned.m16n8k16.row.col.f32.bf16.bf16.f32 "
                        "{%0,%1,%2,%3}, {%4,%5,%6,%7}, {%8,%9}, {%0,%1,%2,%3};\n"
                        : "+f"(acc[mi][nj][0]), "+f"(acc[mi][nj][1]),
                          "+f"(acc[mi][nj][2]), "+f"(acc[mi][nj][3])
                        : "r"(a[mi][0]), "r"(a[mi][1]), "r"(a[mi][2]), "r"(a[mi][3]),
                          "r"(b0), "r"(b1));
                }
            }
        }
        buf ^= 1;
    }

    // Epilogue
    #pragma unroll
    for (int mi = 0; mi < 4; mi++) {
        #pragma unroll
        for (int half = 0; half < 2; half++) {
            int gr = row0 + r0w + mi * 16 + (lane >> 2) + half * 8;
            #pragma unroll
            for (int nj = 0; nj < 4; nj++) {
                #pragma unroll
                for (int q = 0; q < 2; q++) {
                    int gc = col0 + n0w + nj * 8 + (lane & 3) * 2 + q;
                    if (gc >= Nout) continue;
                    float v = acc[mi][nj][half * 2 + q];
                    if (bias) v += bias[gc];
                    if (mode == 0) {
                        Cf[(size_t)gr * ldc + gc] = v;
                    } else {
                        v = eluf(v);
                        __nv_bfloat16 h, l;
                        split_bf16(v, h, l);
                        size_t o = (size_t)gr * lds + gc;
                        hi1[o] = h; hi2[o] = h; lo[o] = l;
                    }
                }
            }
        }
    }
}

// ---------------------------------------------------------------------------
// fp32 SIMT GEMM (only for the tiny 400x400x6400 Weff precompute)
// ---------------------------------------------------------------------------
#define BM 128
#define BN 128
#define BK 8
__global__ __launch_bounds__(256)
void gemm_kernel(const float* __restrict__ A, const float* __restrict__ B,
                 float* __restrict__ C, int M, int N, int K)
{
    __shared__ float As[BK][BM];
    __shared__ float Bs[BK][BN];
    const int tid = threadIdx.x;
    const int tx  = tid % 16;
    const int ty  = tid / 16;
    const int row0 = blockIdx.y * BM;
    const int col0 = blockIdx.x * BN;

    float acc[8][8];
    #pragma unroll
    for (int i = 0; i < 8; i++)
        #pragma unroll
        for (int j = 0; j < 8; j++) acc[i][j] = 0.f;

    for (int k0 = 0; k0 < K; k0 += BK) {
        #pragma unroll
        for (int i = tid; i < BM * BK; i += 256) {
            int r = i / BK, c = i % BK;
            int gr = row0 + r;
            As[c][r] = (gr < M) ? A[(size_t)gr * K + k0 + c] : 0.f;
        }
        #pragma unroll
        for (int i = tid; i < BK * BN; i += 256) {
            int r = i / BN, c = i % BN;
            int gc = col0 + c;
            Bs[r][c] = (gc < N) ? B[(size_t)(k0 + r) * N + gc] : 0.f;
        }
        __syncthreads();
        #pragma unroll
        for (int kk = 0; kk < BK; kk++) {
            float a[8], b[8];
            #pragma unroll
            for (int i = 0; i < 8; i++) a[i] = As[kk][ty * 8 + i];
            #pragma unroll
            for (int j = 0; j < 8; j++) b[j] = Bs[kk][tx * 8 + j];
            #pragma unroll
            for (int i = 0; i < 8; i++)
                #pragma unroll
                for (int j = 0; j < 8; j++) acc[i][j] = fmaf(a[i], b[j], acc[i][j]);
        }
        __syncthreads();
    }
    #pragma unroll
    for (int i = 0; i < 8; i++) {
        int gr = row0 + ty * 8 + i;
        if (gr >= M) continue;
        #pragma unroll
        for (int j = 0; j < 8; j++) {
            int gc = col0 + tx * 8 + j;
            if (gc < N) C[(size_t)gr * N + gc] = acc[i][j];
        }
    }
}

__global__ void beff_kernel(const float* __restrict__ bv,
                            const float* __restrict__ Wo,
                            const float* __restrict__ bo)
{
    int j = blockIdx.x * blockDim.x + threadIdx.x;
    if (j >= DMODEL) return;
    float s = bo[j];
    for (int p = 0; p < PDIM; p++) s = fmaf(bv[p], Wo[(size_t)p * DMODEL + j], s);
    g_beff[j] = s;
}

// ---------------------------------------------------------------------------
// Weight split: src(K0 x N) fp32 -> dst bf16 (ld=Npad), hi rows duplicated at
// off_hi1/off_hi2, lo rows at off_lo; cols >= N zero-padded.
// ---------------------------------------------------------------------------
__global__ void split_w(const float* __restrict__ src, __nv_bfloat16* __restrict__ dst,
                        int K0, int N, int Npad,
                        int off_hi1, int off_hi2, int off_lo)
{
    size_t idx = (size_t)blockIdx.x * blockDim.x + threadIdx.x;
    if (idx >= (size_t)K0 * Npad) return;
    int k = (int)(idx / Npad);
    int n = (int)(idx % Npad);
    float v = (n < N) ? src[(size_t)k * N + n] : 0.f;
    __nv_bfloat16 h, l;
    split_bf16(v, h, l);
    dst[(size_t)(off_hi1 + k) * Npad + n] = h;
    dst[(size_t)(off_hi2 + k) * Npad + n] = h;
    dst[(size_t)(off_lo  + k) * Npad + n] = l;
}

// ---------------------------------------------------------------------------
// Fused encoder: attn (xe@Weff+beff), LN1, rank-2 FFN, LN2; writes split
// bf16 flatE = [hi(1600) | lo(1600) | hi(1600)] per row.
// ---------------------------------------------------------------------------
__global__ __launch_bounds__(512)
void row_kernel(const float* __restrict__ x,
                const float* __restrict__ ln1g, const float* __restrict__ ln1b,
                const float* __restrict__ fw1,  const float* __restrict__ fb1,
                const float* __restrict__ fw2,  const float* __restrict__ fb2,
                const float* __restrict__ ln2g, const float* __restrict__ ln2b)
{
    __shared__ float xs[16][DMODEL];
    const int tid = threadIdx.x;
    const int r0  = blockIdx.x * 16;

    for (int i = tid; i < 16 * 1200; i += 512) {
        int r = i / 1200, c = i % 1200;
        int gr = r0 + r;
        float v = x[(size_t)gr * 1200 + c];
        __nv_bfloat16 h, l;
        split_bf16(v, h, l);
        size_t base = (size_t)gr * FLATE;
        g_flatE[base + c]        = h;
        g_flatE[base + 1600 + c] = l;
        g_flatE[base + 3200 + c] = h;
        if (c >= 800) xs[r][c - 800] = v;
    }
    __syncthreads();

    if (r0 == 0) {
        for (int j = tid; j < DMODEL; j += 512) {
            __nv_bfloat16 h, l;
            split_bf16(xs[0][j], h, l);
            g_flatE[1200 + j] = h;
            g_flatE[2800 + j] = l;
            g_flatE[4400 + j] = h;
        }
    }

    // attn: thread j computes column j for all 16 rows
    float acc[16];
    if (tid < DMODEL) {
        #pragma unroll
        for (int r = 0; r < 16; r++) acc[r] = 0.f;
        for (int k = 0; k < DMODEL; k++) {
            float w = g_Weff[k * DMODEL + tid];
            #pragma unroll
            for (int r = 0; r < 16; r++) acc[r] = fmaf(xs[r][k], w, acc[r]);
        }
    }
    __syncthreads();
    if (tid < DMODEL) {
        float be = g_beff[tid];
        #pragma unroll
        for (int r = 0; r < 16; r++) xs[r][tid] = xs[r][tid] + acc[r] + be;
    }
    __syncthreads();

    const int w    = tid / 32;
    const int lane = tid % 32;
    const int gr   = r0 + w;

    float s = 0.f, sq = 0.f;
    for (int j = lane; j < DMODEL; j += 32) { float v = xs[w][j]; s += v; sq += v * v; }
    #pragma unroll
    for (int o = 16; o > 0; o >>= 1) {
        s  += __shfl_xor_sync(0xffffffffu, s, o);
        sq += __shfl_xor_sync(0xffffffffu, sq, o);
    }
    float m    = s / (float)DMODEL;
    float var  = fmaxf(sq / (float)DMODEL - m * m, 0.f);
    float rstd = rsqrtf(var + 1e-6f);

    float d0 = 0.f, d1 = 0.f;
    for (int j = lane; j < DMODEL; j += 32) {
        float o1 = (xs[w][j] - m) * rstd * ln1g[j] + ln1b[j];
        xs[w][j] = o1;
        d0 = fmaf(o1, fw1[j * 2 + 0], d0);
        d1 = fmaf(o1, fw1[j * 2 + 1], d1);
    }
    #pragma unroll
    for (int o = 16; o > 0; o >>= 1) {
        d0 += __shfl_xor_sync(0xffffffffu, d0, o);
        d1 += __shfl_xor_sync(0xffffffffu, d1, o);
    }
    float h0 = fmaxf(d0 + fb1[0], 0.f);
    float h1 = fmaxf(d1 + fb1[1], 0.f);

    float s2 = 0.f, sq2 = 0.f;
    for (int j = lane; j < DMODEL; j += 32) {
        float t = xs[w][j] + h0 * fw2[j] + h1 * fw2[DMODEL + j] + fb2[j];
        xs[w][j] = t;
        s2 += t; sq2 += t * t;
    }
    #pragma unroll
    for (int o = 16; o > 0; o >>= 1) {
        s2  += __shfl_xor_sync(0xffffffffu, s2, o);
        sq2 += __shfl_xor_sync(0xffffffffu, sq2, o);
    }
    float m2    = s2 / (float)DMODEL;
    float var2  = fmaxf(sq2 / (float)DMODEL - m2 * m2, 0.f);
    float rstd2 = rsqrtf(var2 + 1e-6f);

    if (gr != 0) {
        for (int j = lane; j < DMODEL; j += 32) {
            float v = (xs[w][j] - m2) * rstd2 * ln2g[j] + ln2b[j];
            __nv_bfloat16 h, l;
            split_bf16(v, h, l);
            size_t base = (size_t)gr * FLATE;
            g_flatE[base + 1200 + j] = h;
            g_flatE[base + 2800 + j] = l;
            g_flatE[base + 4400 + j] = h;
        }
    }
}

// ---------------------------------------------------------------------------
// GRU gate epilogue (h0=0); writes split bf16 into catE at x1 columns.
// ---------------------------------------------------------------------------
__global__ void gru_epi_kernel(const float* __restrict__ G,
                               const float* __restrict__ B1, int coloff)
{
    size_t idx = (size_t)blockIdx.x * blockDim.x + threadIdx.x;
    if (idx >= (size_t)NROWS * GUC) return;
    int mrow = (int)(idx / GUC);
    int j    = (int)(idx % GUC);
    size_t base = (size_t)mrow * G3;
    float xz = G[base + j];
    float xr = G[base + GUC + j];
    float xh = G[base + 2 * GUC + j];
    float z  = sigmoidf_(xz + B1[j]);
    float r  = sigmoidf_(xr + B1[GUC + j]);
    float hh = eluf(xh + r * B1[2 * GUC + j]);
    float h  = (1.f - z) * hh;

    __nv_bfloat16 hi, lo;
    split_bf16(h, hi, lo);
    int c = coloff + j;
    size_t o = (size_t)mrow * CATE;
    g_catE[o + c]        = hi;
    g_catE[o + 3600 + c] = lo;
    g_catE[o + 7200 + c] = hi;
}

// ---------------------------------------------------------------------------
// Launch
// ---------------------------------------------------------------------------
extern "C" void kernel_launch(void* const* d_in, const int* in_sizes, int n_in,
                              void* d_out, int out_size)
{
    const bool dict = (in_sizes[10] == 800);

    const float* x  = (const float*)d_in[0];
    const float* Wv = (const float*)d_in[5];
    const float* bv = (const float*)d_in[6];
    const float* Wo = (const float*)d_in[7];
    const float* bo = (const float*)d_in[8];

    const float *ln1g, *ln1b, *fw1, *fb1, *fw2, *fb2, *ln2g, *ln2b;
    const float *gfk, *gfb, *gbk, *gbb, *d2w, *d2b, *d4w, *d4b, *ow, *ob;
    if (dict) {
        ln1b = (const float*)d_in[9];
        fw1  = (const float*)d_in[10]; fb1 = (const float*)d_in[11];
        fw2  = (const float*)d_in[12]; fb2 = (const float*)d_in[13];
        ln2b = (const float*)d_in[14];
        gfk  = (const float*)d_in[15]; gfb = (const float*)d_in[17];
        gbk  = (const float*)d_in[18]; gbb = (const float*)d_in[20];
        d2w  = (const float*)d_in[21]; d2b = (const float*)d_in[22];
        d4w  = (const float*)d_in[23]; d4b = (const float*)d_in[24];
        ow   = (const float*)d_in[25]; ob  = (const float*)d_in[26];
        ln1g = (const float*)d_in[27]; ln2g = (const float*)d_in[28];
    } else {
        ln1g = (const float*)d_in[9];  ln1b = (const float*)d_in[10];
        fw1  = (const float*)d_in[11]; fb1 = (const float*)d_in[12];
        fw2  = (const float*)d_in[13]; fb2 = (const float*)d_in[14];
        ln2g = (const float*)d_in[15]; ln2b = (const float*)d_in[16];
        gfk  = (const float*)d_in[17]; gfb = (const float*)d_in[19];
        gbk  = (const float*)d_in[20]; gbb = (const float*)d_in[22];
        d2w  = (const float*)d_in[23]; d2b = (const float*)d_in[24];
        d4w  = (const float*)d_in[25]; d4b = (const float*)d_in[26];
        ow   = (const float*)d_in[27]; ob  = (const float*)d_in[28];
    }
    float* out = (float*)d_out;

    float *Weff, *G;
    __nv_bfloat16 *flatE, *gfkE, *gbkE, *d2wE, *d4wE, *owE, *catE;
    cudaGetSymbolAddress((void**)&Weff,  g_Weff);
    cudaGetSymbolAddress((void**)&G,     g_G);
    cudaGetSymbolAddress((void**)&flatE, g_flatE);
    cudaGetSymbolAddress((void**)&gfkE,  g_gfkE);
    cudaGetSymbolAddress((void**)&gbkE,  g_gbkE);
    cudaGetSymbolAddress((void**)&d2wE,  g_d2wE);
    cudaGetSymbolAddress((void**)&d4wE,  g_d4wE);
    cudaGetSymbolAddress((void**)&owE,   g_owE);
    cudaGetSymbolAddress((void**)&catE,  g_catE);

    // 1) Attention collapse precompute (fp32, tiny)
    gemm_kernel<<<dim3(4, 4), 256>>>(Wv, Wo, Weff, DMODEL, DMODEL, PDIM);
    beff_kernel<<<2, 256>>>(bv, Wo, bo);

    // 2) Weight splits (hi;hi;lo row-block expansion)
    {
        auto launch_split = [&](const float* s, __nv_bfloat16* d, int K0, int N, int Np,
                                int o1, int o2, int o3) {
            size_t tot = (size_t)K0 * Np;
            split_w<<<(unsigned)((tot + 255) / 256), 256>>>(s, d, K0, N, Np, o1, o2, o3);
        };
        launch_split(gfk, gfkE, FLATK, G3, G3, 0, FLATK, 2 * FLATK);
        launch_split(gbk, gbkE, FLATK, G3, G3, 0, FLATK, 2 * FLATK);
        launch_split(d2w, d2wE, X1C, GUC, GUC, 0, X1C, 2 * X1C);
        launch_split(d4w, d4wE, GUC, GUC, GUC, 0, GUC, 2 * GUC);
        launch_split(ow,                      owE, X1C, OUTC, OWPAD, 0,     X1C,   7200);
        launch_split(ow + (size_t)X1C * OUTC, owE, GUC, OUTC, OWPAD, 10800, 12600, 14400);
        launch_split(ow + (size_t)G3  * OUTC, owE, GUC, OUTC, OWPAD, 16200, 18000, 19800);
    }

    // 3) Fused encoder -> flatE
    row_kernel<<<NROWS / 16, 512>>>(x, ln1g, ln1b, fw1, fb1, fw2, fb2, ln2g, ln2b);

    const unsigned epi_blocks = (unsigned)(((size_t)NROWS * GUC + 255) / 256);

    // 4) Forward GRU
    mma_gemm<<<dim3((G3 + TBN - 1) / TBN, NROWS / TBM), 256>>>(
        flatE, gfkE, gfb, NROWS, G3, FLATE, FLATE, G3,
        0, G, G3, nullptr, nullptr, nullptr, 0, G3);
    gru_epi_kernel<<<epi_blocks, 256>>>(G, gfb + G3, 0);

    // 5) Backward GRU
    mma_gemm<<<dim3((G3 + TBN - 1) / TBN, NROWS / TBM), 256>>>(
        flatE, gbkE, gbb, NROWS, G3, FLATE, FLATE, G3,
        0, G, G3, nullptr, nullptr, nullptr, 0, G3);
    gru_epi_kernel<<<epi_blocks, 256>>>(G, gbb + G3, GUC);

    // 6) x3 = elu(x1 @ d2w + d2b) -> catE cols [10800,16200)
    mma_gemm<<<dim3((GUC + TBN - 1) / TBN, NROWS / TBM), 256>>>(
        catE, d2wE, d2b, NROWS, GUC, 3 * X1C, CATE, GUC,
        2, nullptr, 0, catE + 10800, catE + 14400, catE + 12600, CATE, GUC);

    // 7) x5 = elu(x3 @ d4w + d4b) -> catE cols [16200,21600)
    mma_gemm<<<dim3((GUC + TBN - 1) / TBN, NROWS / TBM), 256>>>(
        catE + 10800, d4wE, d4b, NROWS, GUC, 3 * GUC, CATE, GUC,
        2, nullptr, 0, catE + 16200, catE + 19800, catE + 18000, CATE, GUC);

    // 8) out = cat @ ow + ob  (single K=21600 GEMM)
    mma_gemm<<<dim3((OWPAD + TBN - 1) / TBN, NROWS / TBM), 256>>>(
        catE, owE, ob, NROWS, OWPAD, CATE, CATE, OWPAD,
        0, out, OUTC, nullptr, nullptr, nullptr, 0, OUTC);
}